// round 2
// baseline (speedup 1.0000x reference)
#include <cuda_runtime.h>

// Problem constants (fixed by the reference)
#define BB   2
#define TT   2048
#define DM   1024
#define NH   16
#define DK   64
#define MTOT (BB * TT)   // 4096

// Scratch (allocation-free rule: __device__ globals)
__device__ float g_Qp[(size_t)MTOT * DM];
__device__ float g_Kp[(size_t)MTOT * DM];
__device__ float g_Vp[(size_t)MTOT * DM];
__device__ float g_Op[(size_t)MTOT * DM];

// ---------------------------------------------------------------------------
// GEMM: Out[m,n] = sum_k X[m,k] * W[n,k] + bias[n]      (x @ W.T + b)
// M=4096, N=1024, K=1024 always; tiles divide evenly, no bounds checks.
// ---------------------------------------------------------------------------
#define GBM 128
#define GBN 128
#define GBK 16

__global__ __launch_bounds__(256, 2)
void gemm_xwt(const float* __restrict__ X, const float* __restrict__ W,
              const float* __restrict__ bias, float* __restrict__ Out,
              int M, int N, int K)
{
    __shared__ float As[GBK][GBM];
    __shared__ float Bs[GBK][GBN];

    const int tid = threadIdx.x;
    const int bm  = blockIdx.y * GBM;
    const int bn  = blockIdx.x * GBN;
    const int tx  = tid & 15;   // 16 thread cols
    const int ty  = tid >> 4;   // 16 thread rows

    float acc[8][8];
#pragma unroll
    for (int i = 0; i < 8; i++)
#pragma unroll
        for (int j = 0; j < 8; j++) acc[i][j] = 0.f;

    for (int k0 = 0; k0 < K; k0 += GBK) {
        // Load 128x16 tiles of X and W, transposed into smem.
        // 512 float4 per tile / 256 threads = 2 each.
#pragma unroll
        for (int i = 0; i < 2; i++) {
            int li = tid + i * 256;
            int r  = li >> 2;
            int c4 = (li & 3) * 4;
            float4 xv = *(const float4*)(X + (size_t)(bm + r) * K + k0 + c4);
            As[c4 + 0][r] = xv.x; As[c4 + 1][r] = xv.y;
            As[c4 + 2][r] = xv.z; As[c4 + 3][r] = xv.w;
            float4 wv = *(const float4*)(W + (size_t)(bn + r) * K + k0 + c4);
            Bs[c4 + 0][r] = wv.x; Bs[c4 + 1][r] = wv.y;
            Bs[c4 + 2][r] = wv.z; Bs[c4 + 3][r] = wv.w;
        }
        __syncthreads();

#pragma unroll
        for (int kk = 0; kk < GBK; kk++) {
            float ra[8], rb[8];
#pragma unroll
            for (int i = 0; i < 8; i += 4) {
                float4 v = *(const float4*)&As[kk][ty * 8 + i];
                ra[i] = v.x; ra[i + 1] = v.y; ra[i + 2] = v.z; ra[i + 3] = v.w;
            }
#pragma unroll
            for (int j = 0; j < 8; j += 4) {
                float4 v = *(const float4*)&Bs[kk][tx * 8 + j];
                rb[j] = v.x; rb[j + 1] = v.y; rb[j + 2] = v.z; rb[j + 3] = v.w;
            }
#pragma unroll
            for (int i = 0; i < 8; i++)
#pragma unroll
                for (int j = 0; j < 8; j++) acc[i][j] += ra[i] * rb[j];
        }
        __syncthreads();
    }

    // Epilogue: add bias, coalesced float4 stores.
    float bcol[8];
#pragma unroll
    for (int j = 0; j < 8; j++) bcol[j] = bias[bn + tx * 8 + j];

#pragma unroll
    for (int i = 0; i < 8; i++) {
        int row = bm + ty * 8 + i;
#pragma unroll
        for (int j = 0; j < 8; j += 4) {
            int col = bn + tx * 8 + j;
            float4 o;
            o.x = acc[i][j + 0] + bcol[j + 0];
            o.y = acc[i][j + 1] + bcol[j + 1];
            o.z = acc[i][j + 2] + bcol[j + 2];
            o.w = acc[i][j + 3] + bcol[j + 3];
            *(float4*)(Out + (size_t)row * N + col) = o;
        }
    }
}

// ---------------------------------------------------------------------------
// Flash attention (fp32, online softmax). One thread owns one query row.
// Block: 128 query rows of one (batch, head). Key tiles of 64 in smem.
// ---------------------------------------------------------------------------
#define ABM 128
#define ABN 64

__global__ __launch_bounds__(128)
void attn_kernel(const float* __restrict__ Q, const float* __restrict__ K,
                 const float* __restrict__ V, const int* __restrict__ mask,
                 const int* __restrict__ causal_p, float* __restrict__ O)
{
    __shared__ float Ks[ABN][DK];
    __shared__ float Vs[ABN][DK];
    __shared__ int   ms[ABN];

    const int r  = threadIdx.x;          // 0..127
    const int q0 = blockIdx.x * ABM;
    const int h  = blockIdx.y;
    const int b  = blockIdx.z;
    const int qi = q0 + r;
    const int causal = causal_p[0];

    const size_t rowbase = ((size_t)(b * TT + qi)) * DM + h * DK;

    // Query row into registers, pre-scaled by 1/sqrt(dk) = 0.125
    float q[DK];
#pragma unroll
    for (int k = 0; k < DK; k += 4) {
        float4 t = *(const float4*)(Q + rowbase + k);
        q[k] = t.x * 0.125f; q[k + 1] = t.y * 0.125f;
        q[k + 2] = t.z * 0.125f; q[k + 3] = t.w * 0.125f;
    }

    float o[DK];
#pragma unroll
    for (int k = 0; k < DK; k++) o[k] = 0.f;
    float m = -1e30f, l = 0.f;

    int ntiles = TT / ABN;
    if (causal) {
        int lim = (q0 + ABM + ABN - 1) / ABN;   // last tile touching the diagonal
        if (lim < ntiles) ntiles = lim;
    }

    for (int kt = 0; kt < ntiles; kt++) {
        const int krow0 = kt * ABN;
        // Load K/V 64x64 tiles, coalesced: 1024 float4 / 128 threads = 8 each.
#pragma unroll
        for (int i = 0; i < 8; i++) {
            int li = r + i * 128;
            int kr = li >> 4;
            int c4 = (li & 15) * 4;
            size_t src = ((size_t)(b * TT + krow0 + kr)) * DM + h * DK + c4;
            *(float4*)&Ks[kr][c4] = *(const float4*)(K + src);
            *(float4*)&Vs[kr][c4] = *(const float4*)(V + src);
        }
        if (r < ABN) ms[r] = mask[b * TT + krow0 + r];
        __syncthreads();

        // Process 64 keys in chunks of 16 (keeps register pressure bounded).
#pragma unroll
        for (int c = 0; c < 4; c++) {
            float s[16];
#pragma unroll
            for (int j = 0; j < 16; j++) {
                float acc = 0.f;
#pragma unroll
                for (int k = 0; k < DK; k += 4) {
                    float4 kv = *(const float4*)&Ks[c * 16 + j][k];  // broadcast LDS
                    acc += q[k] * kv.x + q[k + 1] * kv.y
                         + q[k + 2] * kv.z + q[k + 3] * kv.w;
                }
                s[j] = acc;
            }

            const int kbase = krow0 + c * 16;
#pragma unroll
            for (int j = 0; j < 16; j++) {
                int kj = kbase + j;
                if (ms[c * 16 + j] == 0 || (causal && kj > qi)) s[j] = -1e30f;
            }

            float tm = -1e30f;
#pragma unroll
            for (int j = 0; j < 16; j++) tm = fmaxf(tm, s[j]);
            float mn   = fmaxf(m, tm);
            float corr = __expf(m - mn);
            float ps = 0.f;
#pragma unroll
            for (int j = 0; j < 16; j++) { s[j] = __expf(s[j] - mn); ps += s[j]; }
            l = l * corr + ps;
#pragma unroll
            for (int k = 0; k < DK; k++) o[k] *= corr;
#pragma unroll
            for (int j = 0; j < 16; j++) {
                float pj = s[j];
#pragma unroll
                for (int k = 0; k < DK; k += 4) {
                    float4 vv = *(const float4*)&Vs[c * 16 + j][k];  // broadcast LDS
                    o[k]     += pj * vv.x;
                    o[k + 1] += pj * vv.y;
                    o[k + 2] += pj * vv.z;
                    o[k + 3] += pj * vv.w;
                }
            }
            m = mn;
        }
        __syncthreads();
    }

    float inv = 1.f / l;
#pragma unroll
    for (int k = 0; k < DK; k += 4) {
        float4 t;
        t.x = o[k] * inv; t.y = o[k + 1] * inv;
        t.z = o[k + 2] * inv; t.w = o[k + 3] * inv;
        *(float4*)(O + rowbase + k) = t;
    }
}

// ---------------------------------------------------------------------------
// Launch: 3 projection GEMMs -> attention -> output GEMM. Graph-capturable.
// Inputs (metadata order): q,k,v,Wq,bq,Wk,bk,Wv,bv,Wo,bo,mask,causal
// ---------------------------------------------------------------------------
extern "C" void kernel_launch(void* const* d_in, const int* in_sizes, int n_in,
                              void* d_out, int out_size)
{
    const float* q  = (const float*)d_in[0];
    const float* k  = (const float*)d_in[1];
    const float* v  = (const float*)d_in[2];
    const float* Wq = (const float*)d_in[3];
    const float* bq = (const float*)d_in[4];
    const float* Wk = (const float*)d_in[5];
    const float* bk = (const float*)d_in[6];
    const float* Wv = (const float*)d_in[7];
    const float* bv = (const float*)d_in[8];
    const float* Wo = (const float*)d_in[9];
    const float* bo = (const float*)d_in[10];
    const int*   mask   = (const int*)d_in[11];
    const int*   causal = (const int*)d_in[12];
    float* out = (float*)d_out;

    float *Qp, *Kp, *Vp, *Op;
    cudaGetSymbolAddress((void**)&Qp, g_Qp);
    cudaGetSymbolAddress((void**)&Kp, g_Kp);
    cudaGetSymbolAddress((void**)&Vp, g_Vp);
    cudaGetSymbolAddress((void**)&Op, g_Op);

    dim3 gg(DM / GBN, MTOT / GBM);   // (8, 32)
    gemm_xwt<<<gg, 256>>>(q, Wq, bq, Qp, MTOT, DM, DM);
    gemm_xwt<<<gg, 256>>>(k, Wk, bk, Kp, MTOT, DM, DM);
    gemm_xwt<<<gg, 256>>>(v, Wv, bv, Vp, MTOT, DM, DM);

    dim3 ga(TT / ABM, NH, BB);       // (16, 16, 2)
    attn_kernel<<<ga, 128>>>(Qp, Kp, Vp, mask, causal, Op);

    gemm_xwt<<<gg, 256>>>(Op, Wo, bo, out, MTOT, DM, DM);
}

// round 6
// speedup vs baseline: 1.2660x; 1.2660x over previous
#include <cuda_runtime.h>
#include <cstdint>

// Problem constants (fixed by the reference)
#define BB   2
#define TT   2048
#define DM   1024
#define NH   16
#define DK   64
#define MTOT (BB * TT)   // 4096

// Scratch (allocation-free rule: __device__ globals)
__device__ float g_Qp[(size_t)MTOT * DM];
__device__ float g_Kp[(size_t)MTOT * DM];
__device__ float g_Vp[(size_t)MTOT * DM];
__device__ float g_Op[(size_t)MTOT * DM];

// ---------------------------------------------------------------------------
// tf32 helpers (legal on plain sm_103 target: sm_80+ PTX features only)
// ---------------------------------------------------------------------------
__device__ __forceinline__ float tf32r(float x) {   // round-to-nearest tf32
    float y;
    asm("cvt.rna.tf32.f32 %0, %1;" : "=f"(y) : "f"(x));
    return y;
}

__device__ __forceinline__ void mma_tf32(float* c, const uint32_t* a,
                                         const uint32_t* b) {
    asm volatile(
        "mma.sync.aligned.m16n8k8.row.col.f32.tf32.tf32.f32 "
        "{%0,%1,%2,%3}, {%4,%5,%6,%7}, {%8,%9}, {%0,%1,%2,%3};"
        : "+f"(c[0]), "+f"(c[1]), "+f"(c[2]), "+f"(c[3])
        : "r"(a[0]), "r"(a[1]), "r"(a[2]), "r"(a[3]),
          "r"(b[0]), "r"(b[1]));
}

// ===========================================================================
// Tensor-core GEMM:  Out[m,n] = sum_k X[m,k]*W[n,k] + bias[n]    (x @ W.T + b)
// CTA tile 128x128xBK32, 8 warps (2m x 4n), warp tile 64x32 via m16n8k8.
// M=4096, N=K=1024 fixed; tiles divide evenly, no bounds checks.
// ===========================================================================
#define TBM 128
#define TBN 128
#define TBK 32
#define NKT (DM / TBK)          // 32
#define AST (TBK + 4)           // smem row stride in words (pad -> no conflicts)
#define TILE_WORDS (TBM * AST)  // 4608 words per tile buffer

// dynamic smem: As0 | Bs0 | As1 | Bs1
#define SMW_A0 0
#define SMW_B0 (TILE_WORDS)
#define SMW_A1 (2 * TILE_WORDS)
#define SMW_B1 (3 * TILE_WORDS)
#define SM_TOTAL_BYTES (4 * TILE_WORDS * 4)   // 73728

__global__ __launch_bounds__(256, 1)
void gemm_tc(const float* __restrict__ X, const float* __restrict__ W,
             const float* __restrict__ bias, float* __restrict__ Out)
{
    extern __shared__ float smem[];
    const int tid  = threadIdx.x;
    const int lane = tid & 31;
    const int wid  = tid >> 5;        // 0..7
    const int wm   = wid >> 2;        // 0..1  (64-row slab)
    const int wn   = wid & 3;         // 0..3  (32-col slab)
    const int gid  = lane >> 2;       // 0..7
    const int tig  = lane & 3;        // 0..3
    const int bm   = blockIdx.y * TBM;
    const int bn   = blockIdx.x * TBN;

    // per-thread LDG staging coordinates (4 float4 per matrix per tile)
    const int lr  = tid >> 3;         // row 0..? : li>>3 with li = tid + i*256
    const int lc4 = (tid & 7) * 4;    // col word 0,4,...,28

    float acc[4][4][4];
#pragma unroll
    for (int i = 0; i < 4; i++)
#pragma unroll
        for (int j = 0; j < 4; j++)
#pragma unroll
            for (int t = 0; t < 4; t++) acc[i][j][t] = 0.f;

    float4 ra[4], rb[4];

    // ---- prologue: LDG tile 0, STS into buffer 0 ----
#pragma unroll
    for (int i = 0; i < 4; i++) {
        int r = lr + i * 32;
        ra[i] = *(const float4*)(X + (size_t)(bm + r) * DM + lc4);
        rb[i] = *(const float4*)(W + (size_t)(bn + r) * DM + lc4);
    }
#pragma unroll
    for (int i = 0; i < 4; i++) {
        int r = lr + i * 32;
        float* a = smem + SMW_A0 + r * AST + lc4;
        a[0] = tf32r(ra[i].x); a[1] = tf32r(ra[i].y);
        a[2] = tf32r(ra[i].z); a[3] = tf32r(ra[i].w);
        float* b = smem + SMW_B0 + r * AST + lc4;
        b[0] = tf32r(rb[i].x); b[1] = tf32r(rb[i].y);
        b[2] = tf32r(rb[i].z); b[3] = tf32r(rb[i].w);
    }
    __syncthreads();

    const int arow0 = wm * 64 + gid;   // A fragment base row
    const int brow0 = wn * 32 + gid;   // B fragment base row (n index)

    for (int kt = 0; kt < NKT; kt++) {
        // LDG next tile into registers (overlaps with compute below)
        if (kt + 1 < NKT) {
            const int k0 = (kt + 1) * TBK;
#pragma unroll
            for (int i = 0; i < 4; i++) {
                int r = lr + i * 32;
                ra[i] = *(const float4*)(X + (size_t)(bm + r) * DM + k0 + lc4);
                rb[i] = *(const float4*)(W + (size_t)(bn + r) * DM + k0 + lc4);
            }
        }

        // compute on current buffer
        const float* A = smem + ((kt & 1) ? SMW_A1 : SMW_A0);
        const float* B = smem + ((kt & 1) ? SMW_B1 : SMW_B0);
#pragma unroll
        for (int s = 0; s < 4; s++) {            // 4 k-steps of 8
            uint32_t af[4][4], bf[4][2];
#pragma unroll
            for (int i = 0; i < 4; i++) {
                const float* ap = A + (arow0 + i * 16) * AST + s * 8 + tig;
                af[i][0] = __float_as_uint(ap[0]);
                af[i][1] = __float_as_uint(ap[8 * AST]);
                af[i][2] = __float_as_uint(ap[4]);
                af[i][3] = __float_as_uint(ap[8 * AST + 4]);
            }
#pragma unroll
            for (int j = 0; j < 4; j++) {
                const float* bp = B + (brow0 + j * 8) * AST + s * 8 + tig;
                bf[j][0] = __float_as_uint(bp[0]);
                bf[j][1] = __float_as_uint(bp[4]);
            }
#pragma unroll
            for (int i = 0; i < 4; i++)
#pragma unroll
                for (int j = 0; j < 4; j++)
                    mma_tf32(acc[i][j], af[i], bf[j]);
        }

        // STS next tile into the other buffer
        if (kt + 1 < NKT) {
            float* Ad = smem + ((kt & 1) ? SMW_A0 : SMW_A1);
            float* Bd = smem + ((kt & 1) ? SMW_B0 : SMW_B1);
#pragma unroll
            for (int i = 0; i < 4; i++) {
                int r = lr + i * 32;
                float* a = Ad + r * AST + lc4;
                a[0] = tf32r(ra[i].x); a[1] = tf32r(ra[i].y);
                a[2] = tf32r(ra[i].z); a[3] = tf32r(ra[i].w);
                float* b = Bd + r * AST + lc4;
                b[0] = tf32r(rb[i].x); b[1] = tf32r(rb[i].y);
                b[2] = tf32r(rb[i].z); b[3] = tf32r(rb[i].w);
            }
            __syncthreads();
        }
    }

    // ---- epilogue: bias add + float2 stores ----
#pragma unroll
    for (int i = 0; i < 4; i++) {
        const int row0 = bm + wm * 64 + i * 16 + gid;
#pragma unroll
        for (int j = 0; j < 4; j++) {
            const int col = bn + wn * 32 + j * 8 + tig * 2;
            const float b0 = bias[col], b1 = bias[col + 1];
            float2 o0 = make_float2(acc[i][j][0] + b0, acc[i][j][1] + b1);
            float2 o1 = make_float2(acc[i][j][2] + b0, acc[i][j][3] + b1);
            *(float2*)(Out + (size_t)row0 * DM + col)       = o0;
            *(float2*)(Out + (size_t)(row0 + 8) * DM + col) = o1;
        }
    }
}

// ---------------------------------------------------------------------------
// Flash attention (fp32, online softmax). One thread owns one query row.
// ---------------------------------------------------------------------------
#define ABM 128
#define ABN 64

__global__ __launch_bounds__(128)
void attn_kernel(const float* __restrict__ Q, const float* __restrict__ K,
                 const float* __restrict__ V, const int* __restrict__ mask,
                 const int* __restrict__ causal_p, float* __restrict__ O)
{
    __shared__ float Ks[ABN][DK];
    __shared__ float Vs[ABN][DK];
    __shared__ int   ms[ABN];

    const int r  = threadIdx.x;
    const int q0 = blockIdx.x * ABM;
    const int h  = blockIdx.y;
    const int b  = blockIdx.z;
    const int qi = q0 + r;
    const int causal = causal_p[0];

    const size_t rowbase = ((size_t)(b * TT + qi)) * DM + h * DK;

    float q[DK];
#pragma unroll
    for (int k = 0; k < DK; k += 4) {
        float4 t = *(const float4*)(Q + rowbase + k);
        q[k] = t.x * 0.125f; q[k + 1] = t.y * 0.125f;
        q[k + 2] = t.z * 0.125f; q[k + 3] = t.w * 0.125f;
    }

    float o[DK];
#pragma unroll
    for (int k = 0; k < DK; k++) o[k] = 0.f;
    float m = -1e30f, l = 0.f;

    int ntiles = TT / ABN;
    if (causal) {
        int lim = (q0 + ABM + ABN - 1) / ABN;
        if (lim < ntiles) ntiles = lim;
    }

    for (int kt = 0; kt < ntiles; kt++) {
        const int krow0 = kt * ABN;
#pragma unroll
        for (int i = 0; i < 8; i++) {
            int li = r + i * 128;
            int kr = li >> 4;
            int c4 = (li & 15) * 4;
            size_t src = ((size_t)(b * TT + krow0 + kr)) * DM + h * DK + c4;
            *(float4*)&Ks[kr][c4] = *(const float4*)(K + src);
            *(float4*)&Vs[kr][c4] = *(const float4*)(V + src);
        }
        if (r < ABN) ms[r] = mask[b * TT + krow0 + r];
        __syncthreads();

#pragma unroll
        for (int c = 0; c < 4; c++) {
            float s[16];
#pragma unroll
            for (int j = 0; j < 16; j++) {
                float acc = 0.f;
#pragma unroll
                for (int k = 0; k < DK; k += 4) {
                    float4 kv = *(const float4*)&Ks[c * 16 + j][k];
                    acc += q[k] * kv.x + q[k + 1] * kv.y
                         + q[k + 2] * kv.z + q[k + 3] * kv.w;
                }
                s[j] = acc;
            }

            const int kbase = krow0 + c * 16;
#pragma unroll
            for (int j = 0; j < 16; j++) {
                int kj = kbase + j;
                if (ms[c * 16 + j] == 0 || (causal && kj > qi)) s[j] = -1e30f;
            }

            float tm = -1e30f;
#pragma unroll
            for (int j = 0; j < 16; j++) tm = fmaxf(tm, s[j]);
            float mn   = fmaxf(m, tm);
            float corr = __expf(m - mn);
            float ps = 0.f;
#pragma unroll
            for (int j = 0; j < 16; j++) { s[j] = __expf(s[j] - mn); ps += s[j]; }
            l = l * corr + ps;
#pragma unroll
            for (int k = 0; k < DK; k++) o[k] *= corr;
#pragma unroll
            for (int j = 0; j < 16; j++) {
                float pj = s[j];
#pragma unroll
                for (int k = 0; k < DK; k += 4) {
                    float4 vv = *(const float4*)&Vs[c * 16 + j][k];
                    o[k]     += pj * vv.x;
                    o[k + 1] += pj * vv.y;
                    o[k + 2] += pj * vv.z;
                    o[k + 3] += pj * vv.w;
                }
            }
            m = mn;
        }
        __syncthreads();
    }

    float inv = 1.f / l;
#pragma unroll
    for (int k = 0; k < DK; k += 4) {
        float4 t;
        t.x = o[k] * inv; t.y = o[k + 1] * inv;
        t.z = o[k + 2] * inv; t.w = o[k + 3] * inv;
        *(float4*)(O + rowbase + k) = t;
    }
}

// ---------------------------------------------------------------------------
// Launch: 3 projection GEMMs -> attention -> output GEMM. Graph-capturable.
// Inputs (metadata order): q,k,v,Wq,bq,Wk,bk,Wv,bv,Wo,bo,mask,causal
// ---------------------------------------------------------------------------
extern "C" void kernel_launch(void* const* d_in, const int* in_sizes, int n_in,
                              void* d_out, int out_size)
{
    const float* q  = (const float*)d_in[0];
    const float* k  = (const float*)d_in[1];
    const float* v  = (const float*)d_in[2];
    const float* Wq = (const float*)d_in[3];
    const float* bq = (const float*)d_in[4];
    const float* Wk = (const float*)d_in[5];
    const float* bk = (const float*)d_in[6];
    const float* Wv = (const float*)d_in[7];
    const float* bv = (const float*)d_in[8];
    const float* Wo = (const float*)d_in[9];
    const float* bo = (const float*)d_in[10];
    const int*   mask   = (const int*)d_in[11];
    const int*   causal = (const int*)d_in[12];
    float* out = (float*)d_out;

    float *Qp, *Kp, *Vp, *Op;
    cudaGetSymbolAddress((void**)&Qp, g_Qp);
    cudaGetSymbolAddress((void**)&Kp, g_Kp);
    cudaGetSymbolAddress((void**)&Vp, g_Vp);
    cudaGetSymbolAddress((void**)&Op, g_Op);

    static bool attr_set = false;
    if (!attr_set) {
        cudaFuncSetAttribute(gemm_tc, cudaFuncAttributeMaxDynamicSharedMemorySize,
                             SM_TOTAL_BYTES);
        attr_set = true;
    }

    dim3 gg(DM / TBN, MTOT / TBM);   // (8, 32)
    gemm_tc<<<gg, 256, SM_TOTAL_BYTES>>>(q, Wq, bq, Qp);
    gemm_tc<<<gg, 256, SM_TOTAL_BYTES>>>(k, Wk, bk, Kp);
    gemm_tc<<<gg, 256, SM_TOTAL_BYTES>>>(v, Wv, bv, Vp);

    dim3 ga(TT / ABM, NH, BB);       // (16, 16, 2)
    attn_kernel<<<ga, 128>>>(Qp, Kp, Vp, mask, causal, Op);

    gemm_tc<<<gg, 256, SM_TOTAL_BYTES>>>(Op, Wo, bo, out);
}

// round 9
// speedup vs baseline: 5.1100x; 4.0364x over previous
#include <cuda_runtime.h>
#include <cstdint>

// Problem constants (fixed by the reference)
#define BB   2
#define TT   2048
#define DM   1024
#define NH   16
#define DK   64
#define MTOT (BB * TT)   // 4096

// Scratch (allocation-free rule: __device__ globals)
__device__ float g_Qp[(size_t)MTOT * DM];
__device__ float g_Kp[(size_t)MTOT * DM];
__device__ float g_Vp[(size_t)MTOT * DM];
__device__ float g_Op[(size_t)MTOT * DM];

// ---------------------------------------------------------------------------
// tf32 helpers (legal on plain sm_103 target: sm_80+ PTX features only)
// ---------------------------------------------------------------------------
__device__ __forceinline__ float tf32r(float x) {   // round-to-nearest tf32
    float y;
    asm("cvt.rna.tf32.f32 %0, %1;" : "=f"(y) : "f"(x));
    return y;
}

__device__ __forceinline__ void mma_tf32(float* c, const uint32_t* a,
                                         const uint32_t* b) {
    asm volatile(
        "mma.sync.aligned.m16n8k8.row.col.f32.tf32.tf32.f32 "
        "{%0,%1,%2,%3}, {%4,%5,%6,%7}, {%8,%9}, {%0,%1,%2,%3};"
        : "+f"(c[0]), "+f"(c[1]), "+f"(c[2]), "+f"(c[3])
        : "r"(a[0]), "r"(a[1]), "r"(a[2]), "r"(a[3]),
          "r"(b[0]), "r"(b[1]));
}

// ===========================================================================
// Tensor-core GEMM:  Out[m,n] = sum_k X[m,k]*W[n,k] + bias[n]    (x @ W.T + b)
// CTA tile 128x128xBK32, 8 warps (2m x 4n), warp tile 64x32 via m16n8k8.
// (UNCHANGED from round 6 — control for this round's attention change.)
// ===========================================================================
#define TBM 128
#define TBN 128
#define TBK 32
#define NKT (DM / TBK)          // 32
#define AST (TBK + 4)           // smem row stride in words (pad -> no conflicts)
#define TILE_WORDS (TBM * AST)  // 4608 words per tile buffer

#define SMW_A0 0
#define SMW_B0 (TILE_WORDS)
#define SMW_A1 (2 * TILE_WORDS)
#define SMW_B1 (3 * TILE_WORDS)
#define SM_TOTAL_BYTES (4 * TILE_WORDS * 4)   // 73728

__global__ __launch_bounds__(256, 1)
void gemm_tc(const float* __restrict__ X, const float* __restrict__ W,
             const float* __restrict__ bias, float* __restrict__ Out)
{
    extern __shared__ float smem[];
    const int tid  = threadIdx.x;
    const int lane = tid & 31;
    const int wid  = tid >> 5;
    const int wm   = wid >> 2;
    const int wn   = wid & 3;
    const int gid  = lane >> 2;
    const int tig  = lane & 3;
    const int bm   = blockIdx.y * TBM;
    const int bn   = blockIdx.x * TBN;

    const int lr  = tid >> 3;
    const int lc4 = (tid & 7) * 4;

    float acc[4][4][4];
#pragma unroll
    for (int i = 0; i < 4; i++)
#pragma unroll
        for (int j = 0; j < 4; j++)
#pragma unroll
            for (int t = 0; t < 4; t++) acc[i][j][t] = 0.f;

    float4 ra[4], rb[4];

#pragma unroll
    for (int i = 0; i < 4; i++) {
        int r = lr + i * 32;
        ra[i] = *(const float4*)(X + (size_t)(bm + r) * DM + lc4);
        rb[i] = *(const float4*)(W + (size_t)(bn + r) * DM + lc4);
    }
#pragma unroll
    for (int i = 0; i < 4; i++) {
        int r = lr + i * 32;
        float* a = smem + SMW_A0 + r * AST + lc4;
        a[0] = tf32r(ra[i].x); a[1] = tf32r(ra[i].y);
        a[2] = tf32r(ra[i].z); a[3] = tf32r(ra[i].w);
        float* b = smem + SMW_B0 + r * AST + lc4;
        b[0] = tf32r(rb[i].x); b[1] = tf32r(rb[i].y);
        b[2] = tf32r(rb[i].z); b[3] = tf32r(rb[i].w);
    }
    __syncthreads();

    const int arow0 = wm * 64 + gid;
    const int brow0 = wn * 32 + gid;

    for (int kt = 0; kt < NKT; kt++) {
        if (kt + 1 < NKT) {
            const int k0 = (kt + 1) * TBK;
#pragma unroll
            for (int i = 0; i < 4; i++) {
                int r = lr + i * 32;
                ra[i] = *(const float4*)(X + (size_t)(bm + r) * DM + k0 + lc4);
                rb[i] = *(const float4*)(W + (size_t)(bn + r) * DM + k0 + lc4);
            }
        }

        const float* A = smem + ((kt & 1) ? SMW_A1 : SMW_A0);
        const float* B = smem + ((kt & 1) ? SMW_B1 : SMW_B0);
#pragma unroll
        for (int s = 0; s < 4; s++) {
            uint32_t af[4][4], bf[4][2];
#pragma unroll
            for (int i = 0; i < 4; i++) {
                const float* ap = A + (arow0 + i * 16) * AST + s * 8 + tig;
                af[i][0] = __float_as_uint(ap[0]);
                af[i][1] = __float_as_uint(ap[8 * AST]);
                af[i][2] = __float_as_uint(ap[4]);
                af[i][3] = __float_as_uint(ap[8 * AST + 4]);
            }
#pragma unroll
            for (int j = 0; j < 4; j++) {
                const float* bp = B + (brow0 + j * 8) * AST + s * 8 + tig;
                bf[j][0] = __float_as_uint(bp[0]);
                bf[j][1] = __float_as_uint(bp[4]);
            }
#pragma unroll
            for (int i = 0; i < 4; i++)
#pragma unroll
                for (int j = 0; j < 4; j++)
                    mma_tf32(acc[i][j], af[i], bf[j]);
        }

        if (kt + 1 < NKT) {
            float* Ad = smem + ((kt & 1) ? SMW_A0 : SMW_A1);
            float* Bd = smem + ((kt & 1) ? SMW_B0 : SMW_B1);
#pragma unroll
            for (int i = 0; i < 4; i++) {
                int r = lr + i * 32;
                float* a = Ad + r * AST + lc4;
                a[0] = tf32r(ra[i].x); a[1] = tf32r(ra[i].y);
                a[2] = tf32r(ra[i].z); a[3] = tf32r(ra[i].w);
                float* b = Bd + r * AST + lc4;
                b[0] = tf32r(rb[i].x); b[1] = tf32r(rb[i].y);
                b[2] = tf32r(rb[i].z); b[3] = tf32r(rb[i].w);
            }
            __syncthreads();
        }
    }

#pragma unroll
    for (int i = 0; i < 4; i++) {
        const int row0 = bm + wm * 64 + i * 16 + gid;
#pragma unroll
        for (int j = 0; j < 4; j++) {
            const int col = bn + wn * 32 + j * 8 + tig * 2;
            const float b0 = bias[col], b1 = bias[col + 1];
            float2 o0 = make_float2(acc[i][j][0] + b0, acc[i][j][1] + b1);
            float2 o1 = make_float2(acc[i][j][2] + b0, acc[i][j][3] + b1);
            *(float2*)(Out + (size_t)row0 * DM + col)       = o0;
            *(float2*)(Out + (size_t)(row0 + 8) * DM + col) = o1;
        }
    }
}

// ===========================================================================
// Flash attention on tensor cores (tf32 mma.sync, online softmax in the
// accumulator layout). CTA = 4 warps, 64 query rows; each warp owns a 16-row
// slab. K/V tiles of 64 keys in smem (padded strides: K=68, V=72 -> both
// fragment LDS patterns conflict-free).
// ===========================================================================
#define AQT 64            // query rows per CTA
#define AKT 64            // keys per tile
#define KST 68            // Ks row stride (words): bank = gid*4+tig, clean
#define VST 72            // Vs row stride (words): bank = tig*8+gid, clean

__global__ __launch_bounds__(128)
void attn_mma(const float* __restrict__ Q, const float* __restrict__ K,
              const float* __restrict__ V, const int* __restrict__ mask,
              const int* __restrict__ causal_p, float* __restrict__ O)
{
    __shared__ float Ks[AKT * KST];
    __shared__ float Vs[AKT * VST];
    __shared__ int   ms[AKT];

    const int tid  = threadIdx.x;
    const int lane = tid & 31;
    const int wid  = tid >> 5;         // 0..3
    const int gid  = lane >> 2;        // 0..7
    const int tig  = lane & 3;         // 0..3
    const int q0   = blockIdx.x * AQT;
    const int h    = blockIdx.y;
    const int b    = blockIdx.z;
    const int causal = causal_p[0];

    const int qw   = q0 + wid * 16;            // warp's first q row
    const int row0 = qw + gid;                 // this thread's rows
    const int row1 = row0 + 8;

    // ---- persistent Q A-fragments (scaled by 1/8, tf32-rounded) ----
    uint32_t aQ[8][4];
    {
        const float* q0p = Q + ((size_t)(b * TT + row0)) * DM + h * DK;
        const float* q1p = Q + ((size_t)(b * TT + row1)) * DM + h * DK;
#pragma unroll
        for (int s = 0; s < 8; s++) {
            aQ[s][0] = __float_as_uint(tf32r(q0p[s * 8 + tig]     * 0.125f));
            aQ[s][1] = __float_as_uint(tf32r(q1p[s * 8 + tig]     * 0.125f));
            aQ[s][2] = __float_as_uint(tf32r(q0p[s * 8 + tig + 4] * 0.125f));
            aQ[s][3] = __float_as_uint(tf32r(q1p[s * 8 + tig + 4] * 0.125f));
        }
    }

    float o[8][4];
#pragma unroll
    for (int d = 0; d < 8; d++)
#pragma unroll
        for (int t = 0; t < 4; t++) o[d][t] = 0.f;
    float m0 = -1e30f, m1 = -1e30f, l0 = 0.f, l1 = 0.f;

    int ntiles = TT / AKT;
    if (causal) {
        int lim = q0 / AKT + 1;        // last tile touching this CTA's diagonal
        if (lim < ntiles) ntiles = lim;
    }

    for (int kt = 0; kt < ntiles; kt++) {
        const int kbase = kt * AKT;

        // ---- load K/V tile (tf32-rounded) + mask ----
#pragma unroll
        for (int i = 0; i < 8; i++) {
            int li = tid + i * 128;            // 0..1023
            int kr = li >> 4;                  // key row 0..63
            int c4 = (li & 15) * 4;            // col 0,4,..,60
            size_t src = ((size_t)(b * TT + kbase + kr)) * DM + h * DK + c4;
            float4 kv = *(const float4*)(K + src);
            float* kd = &Ks[kr * KST + c4];
            kd[0] = tf32r(kv.x); kd[1] = tf32r(kv.y);
            kd[2] = tf32r(kv.z); kd[3] = tf32r(kv.w);
            float4 vv = *(const float4*)(V + src);
            float* vd = &Vs[kr * VST + c4];
            vd[0] = tf32r(vv.x); vd[1] = tf32r(vv.y);
            vd[2] = tf32r(vv.z); vd[3] = tf32r(vv.w);
        }
        if (tid < AKT) ms[tid] = mask[b * TT + kbase + tid];
        __syncthreads();

        // ---- S = Q @ K^T : 8 n-blocks x 8 k-steps ----
        float s[8][4];
#pragma unroll
        for (int j = 0; j < 8; j++) {
            s[j][0] = 0.f; s[j][1] = 0.f; s[j][2] = 0.f; s[j][3] = 0.f;
            const float* kp = &Ks[(j * 8 + gid) * KST + tig];
#pragma unroll
            for (int st = 0; st < 8; st++) {
                uint32_t bf[2];
                bf[0] = __float_as_uint(kp[st * 8]);
                bf[1] = __float_as_uint(kp[st * 8 + 4]);
                mma_tf32(s[j], aQ[st], bf);
            }
        }

        // ---- mask (padding + causal) ----
#pragma unroll
        for (int j = 0; j < 8; j++) {
            const int c0 = kbase + j * 8 + 2 * tig;
            const int mk0 = ms[j * 8 + 2 * tig];
            const int mk1 = ms[j * 8 + 2 * tig + 1];
            if (mk0 == 0 || (causal && c0 > row0))     s[j][0] = -1e30f;
            if (mk1 == 0 || (causal && c0 + 1 > row0)) s[j][1] = -1e30f;
            if (mk0 == 0 || (causal && c0 > row1))     s[j][2] = -1e30f;
            if (mk1 == 0 || (causal && c0 + 1 > row1)) s[j][3] = -1e30f;
        }

        // ---- online softmax (row reductions over tig-quads) ----
        float tm0 = -1e30f, tm1 = -1e30f;
#pragma unroll
        for (int j = 0; j < 8; j++) {
            tm0 = fmaxf(tm0, fmaxf(s[j][0], s[j][1]));
            tm1 = fmaxf(tm1, fmaxf(s[j][2], s[j][3]));
        }
        tm0 = fmaxf(tm0, __shfl_xor_sync(0xffffffffu, tm0, 1));
        tm0 = fmaxf(tm0, __shfl_xor_sync(0xffffffffu, tm0, 2));
        tm1 = fmaxf(tm1, __shfl_xor_sync(0xffffffffu, tm1, 1));
        tm1 = fmaxf(tm1, __shfl_xor_sync(0xffffffffu, tm1, 2));

        const float mn0 = fmaxf(m0, tm0);
        const float mn1 = fmaxf(m1, tm1);
        const float corr0 = __expf(m0 - mn0);
        const float corr1 = __expf(m1 - mn1);

        float ps0 = 0.f, ps1 = 0.f;
#pragma unroll
        for (int j = 0; j < 8; j++) {
            s[j][0] = __expf(s[j][0] - mn0);
            s[j][1] = __expf(s[j][1] - mn0);
            s[j][2] = __expf(s[j][2] - mn1);
            s[j][3] = __expf(s[j][3] - mn1);
            ps0 += s[j][0] + s[j][1];
            ps1 += s[j][2] + s[j][3];
        }
        ps0 += __shfl_xor_sync(0xffffffffu, ps0, 1);
        ps0 += __shfl_xor_sync(0xffffffffu, ps0, 2);
        ps1 += __shfl_xor_sync(0xffffffffu, ps1, 1);
        ps1 += __shfl_xor_sync(0xffffffffu, ps1, 2);
        l0 = l0 * corr0 + ps0;
        l1 = l1 * corr1 + ps1;
        m0 = mn0; m1 = mn1;

#pragma unroll
        for (int d = 0; d < 8; d++) {
            o[d][0] *= corr0; o[d][1] *= corr0;
            o[d][2] *= corr1; o[d][3] *= corr1;
        }

        // ---- O += P @ V : k-step s2 = P block s2, via shuffle transpose ----
        const int src0 = (lane & ~3) | (tig >> 1);
        const int src1 = src0 + 2;
#pragma unroll
        for (int s2 = 0; s2 < 8; s2++) {
            float v0, v1;
            uint32_t aP[4];
            // row gid: cols tig, tig+4
            v0 = __shfl_sync(0xffffffffu, s[s2][0], src0);
            v1 = __shfl_sync(0xffffffffu, s[s2][1], src0);
            aP[0] = __float_as_uint(tf32r((tig & 1) ? v1 : v0));
            v0 = __shfl_sync(0xffffffffu, s[s2][0], src1);
            v1 = __shfl_sync(0xffffffffu, s[s2][1], src1);
            aP[2] = __float_as_uint(tf32r((tig & 1) ? v1 : v0));
            // row gid+8
            v0 = __shfl_sync(0xffffffffu, s[s2][2], src0);
            v1 = __shfl_sync(0xffffffffu, s[s2][3], src0);
            aP[1] = __float_as_uint(tf32r((tig & 1) ? v1 : v0));
            v0 = __shfl_sync(0xffffffffu, s[s2][2], src1);
            v1 = __shfl_sync(0xffffffffu, s[s2][3], src1);
            aP[3] = __float_as_uint(tf32r((tig & 1) ? v1 : v0));

            const float* vp = &Vs[(s2 * 8 + tig) * VST + gid];
#pragma unroll
            for (int d = 0; d < 8; d++) {
                uint32_t bf[2];
                bf[0] = __float_as_uint(vp[d * 8]);
                bf[1] = __float_as_uint(vp[4 * VST + d * 8]);
                mma_tf32(o[d], aP, bf);
            }
        }
        __syncthreads();
    }

    // ---- epilogue ----
    const float inv0 = 1.f / l0;
    const float inv1 = 1.f / l1;
    float* o0p = O + ((size_t)(b * TT + row0)) * DM + h * DK;
    float* o1p = O + ((size_t)(b * TT + row1)) * DM + h * DK;
#pragma unroll
    for (int d = 0; d < 8; d++) {
        const int col = d * 8 + 2 * tig;
        *(float2*)(o0p + col) = make_float2(o[d][0] * inv0, o[d][1] * inv0);
        *(float2*)(o1p + col) = make_float2(o[d][2] * inv1, o[d][3] * inv1);
    }
}

// ---------------------------------------------------------------------------
// Launch: 3 projection GEMMs -> attention -> output GEMM. Graph-capturable.
// Inputs (metadata order): q,k,v,Wq,bq,Wk,bk,Wv,bv,Wo,bo,mask,causal
// ---------------------------------------------------------------------------
extern "C" void kernel_launch(void* const* d_in, const int* in_sizes, int n_in,
                              void* d_out, int out_size)
{
    const float* q  = (const float*)d_in[0];
    const float* k  = (const float*)d_in[1];
    const float* v  = (const float*)d_in[2];
    const float* Wq = (const float*)d_in[3];
    const float* bq = (const float*)d_in[4];
    const float* Wk = (const float*)d_in[5];
    const float* bk = (const float*)d_in[6];
    const float* Wv = (const float*)d_in[7];
    const float* bv = (const float*)d_in[8];
    const float* Wo = (const float*)d_in[9];
    const float* bo = (const float*)d_in[10];
    const int*   mask   = (const int*)d_in[11];
    const int*   causal = (const int*)d_in[12];
    float* out = (float*)d_out;

    float *Qp, *Kp, *Vp, *Op;
    cudaGetSymbolAddress((void**)&Qp, g_Qp);
    cudaGetSymbolAddress((void**)&Kp, g_Kp);
    cudaGetSymbolAddress((void**)&Vp, g_Vp);
    cudaGetSymbolAddress((void**)&Op, g_Op);

    static bool attr_set = false;
    if (!attr_set) {
        cudaFuncSetAttribute(gemm_tc, cudaFuncAttributeMaxDynamicSharedMemorySize,
                             SM_TOTAL_BYTES);
        attr_set = true;
    }

    dim3 gg(DM / TBN, MTOT / TBM);   // (8, 32)
    gemm_tc<<<gg, 256, SM_TOTAL_BYTES>>>(q, Wq, bq, Qp);
    gemm_tc<<<gg, 256, SM_TOTAL_BYTES>>>(k, Wk, bk, Kp);
    gemm_tc<<<gg, 256, SM_TOTAL_BYTES>>>(v, Wv, bv, Vp);

    dim3 ga(TT / AQT, NH, BB);       // (32, 16, 2)
    attn_mma<<<ga, 128>>>(Qp, Kp, Vp, mask, causal, Op);

    gemm_tc<<<gg, 256, SM_TOTAL_BYTES>>>(Op, Wo, bo, out);
}